// round 10
// baseline (speedup 1.0000x reference)
#include <cuda_runtime.h>
#include <math.h>

#define NB 256
#define S  4096
#define FO 8
#define NM 64
#define FM 6
#define EPSF 1e-5f

#define PBLK 32        // proc blocks per instance, 2048 float4 (32 KB) each
#define OSB  4         // opes blocks per instance, 2048 float4 (32 KB) each
#define PCH  2048      // float4 per chunk
#define GRID_T (NB * PBLK + NB * OSB)   // 8192 + 1024

// -------- device scratch (fixed slots; counters self-reset each replay) --------
__device__ float g_part[NB][PBLK][4];        // proc partials: sum, sumsq, nnz
__device__ float g_opart[NB][OSB][2][FO];    // opes partials: sum, sumsq
__device__ unsigned g_cnt[NB],  g_fin[NB];
__device__ unsigned g_ocnt[NB], g_ofin[NB];

__device__ __forceinline__ float warp_sum(float v) {
#pragma unroll
    for (int o = 16; o > 0; o >>= 1) v += __shfl_down_sync(0xffffffffu, v, o);
    return v;
}

__device__ __forceinline__ void wait_for(unsigned* cnt, unsigned target) {
    if (threadIdx.x == 0) {
        volatile unsigned* p = (volatile unsigned*)cnt;
        while (*p < target) __nanosleep(64);
        __threadfence();
    }
    __syncthreads();
}

__device__ __forceinline__ void retire(unsigned* fin, unsigned* cnt, unsigned nCons) {
    if (threadIdx.x == 0) {
        unsigned o = atomicAdd(fin, 1u);
        if (o == nCons - 1) { *cnt = 0u; *fin = 0u; }
    }
}

__global__ void __launch_bounds__(256)
fused_k(const float4* __restrict__ pt, float4* __restrict__ out_proc,
        const float* __restrict__ opes, float4* __restrict__ out_opes,
        const float* __restrict__ mas, float* __restrict__ out_mas,
        const int* __restrict__ nums) {
    extern __shared__ float4 data[];    // 2048 float4 = 32 KB
    const int bid = blockIdx.x;

    if (bid < NB * PBLK) {
        // ================= proc: stats + SMEM-resident normalize =================
        const int b   = bid >> 5;
        const int sub = bid & (PBLK - 1);
        const size_t base = (size_t)b * (S * NM / 4) + (size_t)sub * PCH;
        const float4* src = pt + base;

        float s = 0.f, ss = 0.f, c = 0.f;
#pragma unroll
        for (int k = 0; k < 8; k++) {
            const int i = threadIdx.x + k * 256;
            float4 v = __ldcs(&src[i]);
            data[i] = v;
            s  += (v.x + v.y) + (v.z + v.w);
            ss += (v.x * v.x + v.y * v.y) + (v.z * v.z + v.w * v.w);
            c  += (float)((v.x != 0.f) + (v.y != 0.f) + (v.z != 0.f) + (v.w != 0.f));
        }

        __shared__ float sh[3][8];
        int lane = threadIdx.x & 31, w = threadIdx.x >> 5;
        s = warp_sum(s); ss = warp_sum(ss); c = warp_sum(c);
        if (lane == 0) { sh[0][w] = s; sh[1][w] = ss; sh[2][w] = c; }
        __syncthreads();
        if (threadIdx.x == 0) {
            float ts = 0.f, tss = 0.f, tc = 0.f;
#pragma unroll
            for (int i = 0; i < 8; i++) { ts += sh[0][i]; tss += sh[1][i]; tc += sh[2][i]; }
            g_part[b][sub][0] = ts;
            g_part[b][sub][1] = tss;
            g_part[b][sub][2] = tc;
            __threadfence();
            atomicAdd(&g_cnt[b], 1u);
        }

        wait_for(&g_cnt[b], PBLK);   // siblings are bid-adjacent -> co-resident, tiny skew

        __shared__ float sm, sr;
        if (threadIdx.x < 32) {
            float ps  = g_part[b][threadIdx.x][0];
            float pss = g_part[b][threadIdx.x][1];
            float pc  = g_part[b][threadIdx.x][2];
#pragma unroll
            for (int o = 16; o > 0; o >>= 1) {
                ps  += __shfl_down_sync(0xffffffffu, ps, o);
                pss += __shfl_down_sync(0xffffffffu, pss, o);
                pc  += __shfl_down_sync(0xffffffffu, pc, o);
            }
            if (threadIdx.x == 0) {
                float m   = ps / pc;
                float var = (pss - ps * ps / pc) / (pc - 1.f);
                sm = m;
                sr = 1.f / (sqrtf(var) + EPSF);
            }
        }
        __syncthreads();
        retire(&g_fin[b], &g_cnt[b], PBLK);
        const float m = sm, r = sr;

        float4* dst = out_proc + base;
#pragma unroll
        for (int k = 0; k < 8; k++) {
            const int i = threadIdx.x + k * 256;
            float4 v = data[i];
            float4 o;
            o.x = (v.x != 0.f) ? (v.x - m) * r : 0.f;
            o.y = (v.y != 0.f) ? (v.y - m) * r : 0.f;
            o.z = (v.z != 0.f) ? (v.z - m) * r : 0.f;
            o.w = (v.w != 0.f) ? (v.w - m) * r : 0.f;
            __stcs(&dst[i], o);
        }
    } else {
        // ================= opes: stats + SMEM-resident normalize (+ mas local) =================
        const int ob  = bid - NB * PBLK;
        const int b   = ob >> 2;
        const int sub = ob & (OSB - 1);
        const int n   = nums[b];
        const int r0  = sub * 1024;          // rows [r0, r0+1024)
        const float4* op = ((const float4*)opes) + (size_t)b * 8192;

        __shared__ float4 smas4[NM * FM / 4];   // 96 float4, sub0 only
        __shared__ float  osh[16][8];
        __shared__ float  M[FO], R[FO], mM[FM], mR[FM];

        float sA[FO], qA[FO];
#pragma unroll
        for (int f = 0; f < FO; f++) { sA[f] = 0.f; qA[f] = 0.f; }

#pragma unroll
        for (int k = 0; k < 4; k++) {
            const int r = r0 + threadIdx.x + k * 256;
            float4 a  = __ldcs(&op[r * 2]);
            float4 b4 = __ldcs(&op[r * 2 + 1]);
            data[(r - r0) * 2]     = a;
            data[(r - r0) * 2 + 1] = b4;
            if (r < n) {
                sA[0] += a.x;  qA[0] += a.x * a.x;
                sA[1] += a.y;  qA[1] += a.y * a.y;
                sA[2] += a.z;  qA[2] += a.z * a.z;
                sA[3] += a.w;  qA[3] += a.w * a.w;
                sA[4] += b4.x; qA[4] += b4.x * b4.x;
                sA[5] += b4.y; qA[5] += b4.y * b4.y;
                sA[6] += b4.z; qA[6] += b4.z * b4.z;
                sA[7] += b4.w; qA[7] += b4.w * b4.w;
            }
        }
        if (sub == 0 && threadIdx.x < NM * FM / 4) {
            smas4[threadIdx.x] = ((const float4*)(mas + (size_t)b * NM * FM))[threadIdx.x];
        }

        int lane = threadIdx.x & 31, w = threadIdx.x >> 5;
#pragma unroll
        for (int f = 0; f < FO; f++) {
            float rs = warp_sum(sA[f]);
            float rq = warp_sum(qA[f]);
            if (lane == 0) { osh[f][w] = rs; osh[f + 8][w] = rq; }
        }
        __syncthreads();
        if (threadIdx.x < FO) {
            const int f = threadIdx.x;
            float ts = 0.f, tq = 0.f;
#pragma unroll
            for (int i = 0; i < 8; i++) { ts += osh[f][i]; tq += osh[f + 8][i]; }
            g_opart[b][sub][0][f] = ts;
            g_opart[b][sub][1][f] = tq;
        }
        // mas stats, fully block-local (smas4 complete: written before the sync above)
        if (sub == 0 && threadIdx.x >= 64 && threadIdx.x < 64 + FM) {
            const int f = threadIdx.x - 64;
            const float* sm_ = (const float*)smas4;
            float ts = 0.f, tq = 0.f;
#pragma unroll
            for (int r2 = 0; r2 < NM; r2++) { float x = sm_[r2 * FM + f]; ts += x; tq += x * x; }
            float fm   = (float)NM;
            float mean = ts / fm;
            float var  = (tq - ts * ts / fm) / (fm - 1.f);
            mM[f] = mean;
            mR[f] = 1.f / (sqrtf(var) + EPSF);
        }
        __syncthreads();
        if (threadIdx.x == 0) { __threadfence(); atomicAdd(&g_ocnt[b], 1u); }

        wait_for(&g_ocnt[b], OSB);

        if (threadIdx.x < FO) {
            const int f = threadIdx.x;
            float ts = 0.f, tq = 0.f;
#pragma unroll
            for (int s2 = 0; s2 < OSB; s2++) {
                ts += g_opart[b][s2][0][f];
                tq += g_opart[b][s2][1][f];
            }
            float fn   = (float)n;
            float mean = ts / fn;
            float var  = (tq - ts * ts / fn) / (fn - 1.f);
            M[f] = mean;
            R[f] = 1.f / (sqrtf(var) + EPSF);
        }
        __syncthreads();
        retire(&g_ofin[b], &g_ocnt[b], OSB);

        float4* dst = ((float4*)out_opes) + (size_t)b * 8192 + (size_t)sub * PCH;
#pragma unroll
        for (int k = 0; k < 8; k++) {
            const int i = threadIdx.x + k * 256;
            float4 v = data[i];
            const int g = (i & 1) * 4;     // chunk base is even -> parity preserved
            float4 o;
            o.x = (v.x - M[g + 0]) * R[g + 0];
            o.y = (v.y - M[g + 1]) * R[g + 1];
            o.z = (v.z - M[g + 2]) * R[g + 2];
            o.w = (v.w - M[g + 3]) * R[g + 3];
            __stcs(&dst[i], o);
        }

        if (sub == 0) {
            const float* sm_ = (const float*)smas4;
            float* mout = out_mas + (size_t)b * NM * FM;
            if (threadIdx.x < NM * FM - 256) {
                int i = 256 + threadIdx.x;
                mout[i] = (sm_[i] - mM[i % FM]) * mR[i % FM];
            }
            {
                int i = threadIdx.x;
                mout[i] = (sm_[i] - mM[i % FM]) * mR[i % FM];
            }
        }
    }
}

extern "C" void kernel_launch(void* const* d_in, const int* in_sizes, int n_in,
                              void* d_out, int out_size) {
    const float* raw_opes = (const float*)d_in[0];
    const float* raw_mas  = (const float*)d_in[1];
    const float* proc     = (const float*)d_in[2];
    const int*   nums     = (const int*)d_in[3];

    float* out_opes = (float*)d_out;
    float* out_mas  = out_opes + (size_t)NB * S * FO;
    float* out_proc = out_mas  + (size_t)NB * NM * FM;

    fused_k<<<GRID_T, 256, PCH * 16>>>((const float4*)proc, (float4*)out_proc,
                                       raw_opes, (float4*)out_opes,
                                       raw_mas, out_mas, nums);
}